// round 15
// baseline (speedup 1.0000x reference)
#include <cuda_runtime.h>
#include <cuda_bf16.h>

// FINAL — MyAvgPool2D_56444460204139 on GB300 (sm_103a).
//
// Reference with H=W=56, OUT=56 reduces to a 1x1/stride-1 avgpool ==
// identity: an out-of-place copy of 51,380,224 fp32 (205.5 MB each way,
// 411 MB irreducible HBM traffic; harness poisons d_out).
//
// Converged after 13 benches: all viable configs land in a kernel noise
// band of 56.2-58.2us (~7.1-7.3 TB/s combined, ~90% of the 8 TB/s HBM3e
// spec; residual is intrinsic DRAM read<->write bus turnaround). e2e is
// pinned at 64.0-64.3us incl. ~7us fixed graph-replay overhead.
// Probe matrix, all settled by measurement:
//   - MLP depth: UNROLL=8 float4/thread optimal (4 slower, 16 neutral)
//   - access width: 256-bit LDG/STG neutral vs 128-bit
//   - grid: exact non-persistent cover beats persistent single-wave
//   - cache policy: .cs == .wb on stores; .cs keeps L2 clean
//   - block geometry: 256 ~= 512 (noise; 256 holds the session-best e2e
//     draws and finer retire granularity), 1024 regressed
//
// Submitting the 256-thread shape: best historical e2e (63.97us), highest
// block count => finest scheduling granularity, identical physics.

#define THREADS 256
#define UNROLL  8   // float4s per thread

__global__ __launch_bounds__(THREADS) void copy_kernel(
    const float4* __restrict__ src, float4* __restrict__ dst)
{
    // Each block owns THREADS*UNROLL = 2048 consecutive float4s (32 KB),
    // per-thread accesses strided by THREADS for full coalescing.
    // All loads front-batched (8 outstanding LDG.E.128 per thread), then
    // all stores — longest possible same-direction bursts at the DRAM bus.
    int base = blockIdx.x * (THREADS * UNROLL) + threadIdx.x;

    float4 v[UNROLL];
    #pragma unroll
    for (int u = 0; u < UNROLL; u++)
        v[u] = __ldcs(&src[base + u * THREADS]);
    #pragma unroll
    for (int u = 0; u < UNROLL; u++)
        __stcs(&dst[base + u * THREADS], v[u]);
}

extern "C" void kernel_launch(void* const* d_in, const int* in_sizes, int n_in,
                              void* d_out, int out_size) {
    const float4* x = (const float4*)d_in[0];
    float4* out = (float4*)d_out;
    // out_size = 51,380,224 floats = 12,845,056 float4s
    // = 6272 blocks * (256 threads * 8 float4s). Exact cover, no tail.
    int n4 = out_size / 4;
    int per_block = THREADS * UNROLL;
    int blocks = n4 / per_block;  // 6272
    copy_kernel<<<blocks, THREADS>>>(x, out);
}

// round 16
// speedup vs baseline: 1.0045x; 1.0045x over previous
#include <cuda_runtime.h>
#include <cuda_bf16.h>

// FINAL — MyAvgPool2D_56444460204139 on GB300 (sm_103a).
//
// Reference with H=W=56, OUT=56 reduces to a 1x1/stride-1 avgpool ==
// identity: an out-of-place copy of 51,380,224 fp32 (205.5 MB each way,
// 411 MB irreducible HBM traffic; harness poisons d_out).
//
// Converged after 14 benches: all viable configs land in a kernel noise
// band of 56.2-58.2us (~7.1-7.3 TB/s combined, ~90% of the 8 TB/s HBM3e
// spec; residual is intrinsic DRAM read<->write bus turnaround). e2e is
// pinned at 64.0-64.3us incl. ~7us fixed graph-replay overhead.
// Probe matrix, all settled by measurement:
//   - MLP depth: UNROLL=8 float4/thread optimal (4 slower, 16 neutral)
//   - access width: 256-bit LDG/STG neutral vs 128-bit
//   - grid: exact non-persistent cover beats persistent single-wave
//     (loop back-edge serializes next-tile loads behind prior stores)
//   - cache policy: .cs == .wb on stores; .cs keeps L2 clean
//   - block geometry: 256 ~= 512 (noise), 1024 regressed (occupancy loss
//     + coarser retire granularity)
//
// rel_err = 0.0 on every run (bitwise-exact copy). Locked.

#define THREADS 256
#define UNROLL  8   // float4s per thread

__global__ __launch_bounds__(THREADS) void copy_kernel(
    const float4* __restrict__ src, float4* __restrict__ dst)
{
    // Each block owns THREADS*UNROLL = 2048 consecutive float4s (32 KB),
    // per-thread accesses strided by THREADS for full coalescing.
    // All loads front-batched (8 outstanding LDG.E.128 per thread), then
    // all stores — longest possible same-direction bursts at the DRAM bus.
    int base = blockIdx.x * (THREADS * UNROLL) + threadIdx.x;

    float4 v[UNROLL];
    #pragma unroll
    for (int u = 0; u < UNROLL; u++)
        v[u] = __ldcs(&src[base + u * THREADS]);
    #pragma unroll
    for (int u = 0; u < UNROLL; u++)
        __stcs(&dst[base + u * THREADS], v[u]);
}

extern "C" void kernel_launch(void* const* d_in, const int* in_sizes, int n_in,
                              void* d_out, int out_size) {
    const float4* x = (const float4*)d_in[0];
    float4* out = (float4*)d_out;
    // out_size = 51,380,224 floats = 12,845,056 float4s
    // = 6272 blocks * (256 threads * 8 float4s). Exact cover, no tail.
    int n4 = out_size / 4;
    int per_block = THREADS * UNROLL;
    int blocks = n4 / per_block;  // 6272
    copy_kernel<<<blocks, THREADS>>>(x, out);
}